// round 2
// baseline (speedup 1.0000x reference)
#include <cuda_runtime.h>
#include <cuda_bf16.h>
#include <cstdint>

// Problem constants (fixed by the reference setup_inputs):
//   flows:  [B=4, L=32, 2,  H=128, W=128] fp32
//   images: [B=4, L=32, 16, H=128, W=128] fp32
// Output = images after 5 doubling pscan steps (step = 1,2,4,8,16).

constexpr int B  = 4;
constexpr int L  = 32;
constexpr int C  = 16;
constexpr int H  = 128;
constexpr int W  = 128;
constexpr int HW = H * W;
constexpr int FSTR = 2 * HW;   // floats per (b,t) in flows
constexpr int ISTR = C * HW;   // floats per (b,t) in images
constexpr int NPIX = B * L * HW;

// Allocation-free scratch (module-load-time device globals).
__device__ float g_flowsA[B * L * 2 * HW];   // 16 MiB
__device__ float g_flowsB[B * L * 2 * HW];   // 16 MiB
__device__ float g_imagesA[B * L * C * HW];  // 128 MiB

__global__ __launch_bounds__(256)
void pscan_step_kernel(const float* __restrict__ sf,   // src flows  [B,L,2,H,W]
                       const float* __restrict__ si,   // src images [B,L,C,H,W]
                       float* __restrict__ df,         // dst flows
                       float* __restrict__ di,         // dst images
                       int step)
{
    int idx = blockIdx.x * blockDim.x + threadIdx.x;
    if (idx >= NPIX) return;

    int hw = idx % HW;
    int bt = idx / HW;          // b*L + t
    int t  = bt % L;
    int w  = hw % W;
    int h  = hw / W;

    const float* fcur = sf + (size_t)bt * FSTR + hw;
    const float* icur = si + (size_t)bt * ISTR + hw;
    float*       fo   = df + (size_t)bt * FSTR + hw;
    float*       io   = di + (size_t)bt * ISTR + hw;

    if (t < step) {
        // passthrough copy (fully coalesced)
        fo[0]  = fcur[0];
        fo[HW] = fcur[HW];
        #pragma unroll
        for (int c = 0; c < C; c++) io[c * HW] = icur[c * HW];
        return;
    }

    // --- build sample grid from current flow ---
    float fxv = fcur[0];
    float fyv = fcur[HW];
    float gx = ((float)w + 0.5f) * (2.0f / W) - 1.0f + fxv;
    float gy = ((float)h + 0.5f) * (2.0f / H) - 1.0f + fyv;

    // wrap x: remainder(gx+1, 2) - 1  (python-style mod, result in [0,2))
    float r = fmodf(gx + 1.0f, 2.0f);
    if (r < 0.0f) r += 2.0f;
    float gxw = r - 1.0f;

    // unnormalize (align_corners=False)
    float x = (gxw + 1.0f) * (0.5f * W) - 0.5f;
    float y = (gy  + 1.0f) * (0.5f * H) - 0.5f;

    float x0f = floorf(x);
    float y0f = floorf(y);
    float wx = x - x0f;
    float wy = y - y0f;
    int x0 = (int)x0f, y0 = (int)y0f;
    int x1 = x0 + 1,   y1 = y0 + 1;

    int x0c = min(max(x0, 0), W - 1);
    int x1c = min(max(x1, 0), W - 1);
    int y0c = min(max(y0, 0), H - 1);
    int y1c = min(max(y1, 0), H - 1);

    float w00 = (1.0f - wx) * (1.0f - wy);
    float w01 = wx * (1.0f - wy);
    float w10 = (1.0f - wx) * wy;
    float w11 = wx * wy;

    int o00 = y0c * W + x0c;
    int o01 = y0c * W + x1c;
    int o10 = y1c * W + x0c;
    int o11 = y1c * W + x1c;

    // --- flows: border padding (clamped indices, full weights) ---
    const float* fprev = sf + (size_t)(bt - step) * FSTR;
    #pragma unroll
    for (int c = 0; c < 2; c++) {
        const float* p = fprev + c * HW;
        float v = w00 * p[o00] + w01 * p[o01] + w10 * p[o10] + w11 * p[o11];
        fo[c * HW] = fcur[c * HW] + v;
    }

    // --- images: zeros padding (zero out-of-bounds taps) ---
    bool vx0 = (x0 >= 0) && (x0 < W);
    bool vx1 = (x1 >= 0) && (x1 < W);
    bool vy0 = (y0 >= 0) && (y0 < H);
    bool vy1 = (y1 >= 0) && (y1 < H);
    float z00 = (vy0 && vx0) ? w00 : 0.0f;
    float z01 = (vy0 && vx1) ? w01 : 0.0f;
    float z10 = (vy1 && vx0) ? w10 : 0.0f;
    float z11 = (vy1 && vx1) ? w11 : 0.0f;

    const float* iprev = si + (size_t)(bt - step) * ISTR;
    #pragma unroll
    for (int c = 0; c < C; c++) {
        const float* p = iprev + c * HW;
        float v = z00 * p[o00] + z01 * p[o01] + z10 * p[o10] + z11 * p[o11];
        io[c * HW] = icur[c * HW] + v;
    }
}

extern "C" void kernel_launch(void* const* d_in, const int* in_sizes, int n_in,
                              void* d_out, int out_size)
{
    // metadata order: flows first, images second; guard by size just in case.
    const float* flows  = (const float*)d_in[0];
    const float* images = (const float*)d_in[1];
    if (n_in >= 2 && in_sizes[0] > in_sizes[1]) {
        flows  = (const float*)d_in[1];
        images = (const float*)d_in[0];
    }
    float* out = (float*)d_out;

    float *fA, *fB, *iA;
    cudaGetSymbolAddress((void**)&fA, g_flowsA);
    cudaGetSymbolAddress((void**)&fB, g_flowsB);
    cudaGetSymbolAddress((void**)&iA, g_imagesA);

    const int threads = 256;
    const int blocks  = (NPIX + threads - 1) / threads;

    // 5 steps, odd count: start d_in -> d_out, ping-pong d_out <-> scratch,
    // so the final step lands images in d_out.
    pscan_step_kernel<<<blocks, threads>>>(flows, images, fA, out, 1);
    pscan_step_kernel<<<blocks, threads>>>(fA, out,      fB, iA,  2);
    pscan_step_kernel<<<blocks, threads>>>(fB, iA,       fA, out, 4);
    pscan_step_kernel<<<blocks, threads>>>(fA, out,      fB, iA,  8);
    pscan_step_kernel<<<blocks, threads>>>(fB, iA,       fA, out, 16);
}

// round 3
// speedup vs baseline: 1.0282x; 1.0282x over previous
#include <cuda_runtime.h>
#include <cuda_bf16.h>
#include <cstdint>

// flows:  [B=4, L=32, 2,  H=128, W=128] fp32 (planar everywhere)
// images: [B=4, L=32, 16, H=128, W=128] fp32 planar in/out,
//         channel-interleaved [bt][hw][16] in scratch.
// pscan: 5 doubling steps s = 1,2,4,8,16.
//
// No-copy routing: at step s, writes t in [s,2s) are FINAL -> d_out (planar),
// writes t >= 2s -> alternating scratch (interleaved). Reads of j = t-s:
//   j == 0      -> original input (planar)
//   1 <= j < s  -> d_out (planar, finalized by earlier steps)
//   j >= s      -> previous step's scratch (interleaved; planar input at s=1)

constexpr int B  = 4;
constexpr int L  = 32;
constexpr int C  = 16;
constexpr int H  = 128;
constexpr int W  = 128;
constexpr int HW = H * W;
constexpr int FSTR = 2 * HW;
constexpr int ISTR = C * HW;

// Allocation-free scratch.
__device__ float g_iS0[B * L * ISTR];   // interleaved image scratch A (134 MB)
__device__ float g_iS1[B * L * ISTR];   // interleaved image scratch B (134 MB)
__device__ float g_fS0[B * L * FSTR];   // planar flow scratch A
__device__ float g_fS1[B * L * FSTR];   // planar flow scratch B
__device__ float g_fF [B * L * FSTR];   // planar flow "finals"

struct GridS {
    int o00, o01, o10, o11;
    float w00, w01, w10, w11;   // border-pad weights (flows)
    float z00, z01, z10, z11;   // zeros-pad weights (images)
};

__device__ __forceinline__ GridS make_grid(float fx, float fyv, int w, int h)
{
    GridS g;
    float gx = ((float)w + 0.5f) * (2.0f / W) - 1.0f + fx;
    float gy = ((float)h + 0.5f) * (2.0f / H) - 1.0f + fyv;

    // wrap x: remainder(gx+1, 2) - 1 (python-style mod)
    float r = fmodf(gx + 1.0f, 2.0f);
    if (r < 0.0f) r += 2.0f;
    float gxw = r - 1.0f;

    float x  = (gxw + 1.0f) * (0.5f * W) - 0.5f;
    float yy = (gy  + 1.0f) * (0.5f * H) - 0.5f;

    float x0f = floorf(x);
    float y0f = floorf(yy);
    float wx = x - x0f;
    float wy = yy - y0f;
    int x0 = (int)x0f, y0 = (int)y0f;
    int x1 = x0 + 1,   y1 = y0 + 1;

    int x0c = min(max(x0, 0), W - 1);
    int x1c = min(max(x1, 0), W - 1);
    int y0c = min(max(y0, 0), H - 1);
    int y1c = min(max(y1, 0), H - 1);

    g.w00 = (1.0f - wx) * (1.0f - wy);
    g.w01 = wx * (1.0f - wy);
    g.w10 = (1.0f - wx) * wy;
    g.w11 = wx * wy;

    g.o00 = y0c * W + x0c;
    g.o01 = y0c * W + x1c;
    g.o10 = y1c * W + x0c;
    g.o11 = y1c * W + x1c;

    bool vx0 = (x0 >= 0) && (x0 < W);
    bool vx1 = (x1 >= 0) && (x1 < W);
    bool vy0 = (y0 >= 0) && (y0 < H);
    bool vy1 = (y1 >= 0) && (y1 < H);
    g.z00 = (vy0 && vx0) ? g.w00 : 0.0f;
    g.z01 = (vy0 && vx1) ? g.w01 : 0.0f;
    g.z10 = (vy1 && vx0) ? g.w10 : 0.0f;
    g.z11 = (vy1 && vx1) ? g.w11 : 0.0f;
    return g;
}

// ---------------- t = 0 passthrough (images -> d_out, flows -> g_fF) ----------
__global__ __launch_bounds__(256)
void copy_t0_kernel(const float* __restrict__ iin, const float* __restrict__ fin,
                    float* iout, float* fout)
{
    int n_img = B * ISTR;
    int n_flo = B * FSTR;
    for (int idx = blockIdx.x * blockDim.x + threadIdx.x;
         idx < n_img + n_flo; idx += gridDim.x * blockDim.x) {
        if (idx < n_img) {
            int b = idx / ISTR, r = idx % ISTR;
            size_t off = (size_t)(b * L) * ISTR + r;
            iout[off] = iin[off];
        } else {
            int k = idx - n_img;
            int b = k / FSTR, r = k % FSTR;
            size_t off = (size_t)(b * L) * FSTR + r;
            fout[off] = fin[off];
        }
    }
}

// ---------------- flow step (planar everywhere) ------------------------------
__global__ __launch_bounds__(256)
void flow_step_kernel(const float* __restrict__ fin,    // original flows
                      const float* fF,                   // finals buffer (r/w disjoint)
                      const float* __restrict__ fprev,  // prev scratch (or fin at s=1)
                      float* fFdst,                      // == fF
                      float* __restrict__ fscr,          // cur scratch
                      int s)
{
    int hw = blockIdx.x * blockDim.x + threadIdx.x;
    int Ls = L - s;
    int y  = blockIdx.y;
    int b = y / Ls, trel = y % Ls;
    int t = s + trel, j = trel;
    size_t bt  = (size_t)(b * L + t);
    size_t btj = (size_t)(b * L + j);

    const float* fc = fprev + bt * FSTR;
    float fx  = fc[hw];
    float fyv = fc[HW + hw];
    int w = hw & (W - 1), h = hw >> 7;
    GridS g = make_grid(fx, fyv, w, h);

    const float* src = (j == 0) ? fin + btj * FSTR
                     : (j <  s) ? fF  + btj * FSTR
                                : fprev + btj * FSTR;
    float* dst = ((t < 2 * s) ? fFdst : fscr) + bt * FSTR;

    #pragma unroll
    for (int c = 0; c < 2; c++) {
        const float* p = src + c * HW;
        float v = g.w00 * p[g.o00] + g.w01 * p[g.o01]
                + g.w10 * p[g.o10] + g.w11 * p[g.o11];
        dst[c * HW + hw] = fc[c * HW + hw] + v;
    }
}

// ---------------- image step 1 (planar sources, per-pixel threads) -----------
// t==1 -> planar d_out; t>=2 -> interleaved scratch via smem bounce.
__global__ __launch_bounds__(256)
void img_step1_kernel(const float* __restrict__ iin,
                      const float* __restrict__ fin,
                      float* iFinal,                 // d_out
                      float* __restrict__ iscr)      // g_iS0 (interleaved)
{
    __shared__ float sm[256 * 17];
    int tid = threadIdx.x;
    int p = blockIdx.x * 256 + tid;          // pixel; gridDim.x = 64
    int y = blockIdx.y;                      // B*(L-1)
    int b = y / (L - 1), trel = y % (L - 1);
    int t = 1 + trel, j = trel;
    size_t bt  = (size_t)(b * L + t);
    size_t btj = (size_t)(b * L + j);

    const float* fc = fin + bt * FSTR;
    int w = p & (W - 1), h = p >> 7;
    GridS g = make_grid(fc[p], fc[HW + p], w, h);

    const float* cur = iin + bt  * ISTR;
    const float* src = iin + btj * ISTR;

    if (t == 1) {
        float* dst = iFinal + bt * ISTR;
        #pragma unroll
        for (int c = 0; c < C; c++) {
            const float* q = src + c * HW;
            float v = g.z00 * q[g.o00] + g.z01 * q[g.o01]
                    + g.z10 * q[g.o10] + g.z11 * q[g.o11];
            dst[c * HW + p] = cur[c * HW + p] + v;
        }
    } else {
        #pragma unroll
        for (int c = 0; c < C; c++) {
            const float* q = src + c * HW;
            float v = g.z00 * q[g.o00] + g.z01 * q[g.o01]
                    + g.z10 * q[g.o10] + g.z11 * q[g.o11];
            sm[tid * 17 + c] = cur[c * HW + p] + v;
        }
        __syncthreads();
        float* dst = iscr + bt * ISTR + (size_t)blockIdx.x * 256 * 16;
        #pragma unroll
        for (int k = 0; k < 16; k++) {
            int idx = tid + k * 256;
            dst[idx] = sm[(idx >> 4) * 17 + (idx & 15)];
        }
    }
}

// ---------------- image step s>=2 (interleaved, 4 threads/pixel) -------------
__global__ __launch_bounds__(256)
void img_step_kernel(const float* __restrict__ iin,    // planar original
                     const float* iFin,                 // d_out planar finals (read)
                     const float* __restrict__ iprev,  // prev scratch interleaved
                     float* iFdst,                      // d_out (write)
                     float* __restrict__ iscr,          // cur scratch interleaved
                     const float* __restrict__ fprev,  // planar flows (prev state)
                     int s)
{
    __shared__ float sm[64 * 17];
    int tid = threadIdx.x;
    int chunk = tid & 3;             // 4 channels per thread
    int pl = tid >> 2;               // 64 pixels per block
    int p = blockIdx.x * 64 + pl;    // gridDim.x = 256
    int Ls = L - s;
    int y = blockIdx.y;
    int b = y / Ls, trel = y % Ls;
    int t = s + trel, j = trel;
    size_t bt  = (size_t)(b * L + t);
    size_t btj = (size_t)(b * L + j);

    const float* fc = fprev + bt * FSTR;
    int w = p & (W - 1), h = p >> 7;
    GridS g = make_grid(fc[p], fc[HW + p], w, h);

    // current value (interleaved, coalesced float4)
    float4 cv = *(const float4*)(iprev + bt * ISTR + (size_t)p * 16 + chunk * 4);
    float a0 = cv.x, a1 = cv.y, a2 = cv.z, a3 = cv.w;

    if (j >= s) {
        // interleaved gather: one float4 per tap
        const float* srcp = iprev + btj * ISTR + chunk * 4;
        float4 v00 = *(const float4*)(srcp + (size_t)g.o00 * 16);
        float4 v01 = *(const float4*)(srcp + (size_t)g.o01 * 16);
        float4 v10 = *(const float4*)(srcp + (size_t)g.o10 * 16);
        float4 v11 = *(const float4*)(srcp + (size_t)g.o11 * 16);
        a0 += g.z00 * v00.x + g.z01 * v01.x + g.z10 * v10.x + g.z11 * v11.x;
        a1 += g.z00 * v00.y + g.z01 * v01.y + g.z10 * v10.y + g.z11 * v11.y;
        a2 += g.z00 * v00.z + g.z01 * v01.z + g.z10 * v10.z + g.z11 * v11.z;
        a3 += g.z00 * v00.w + g.z01 * v01.w + g.z10 * v10.w + g.z11 * v11.w;
    } else {
        // planar gather (j==0 -> input, else d_out finals)
        const float* base = (j == 0) ? iin + btj * ISTR : iFin + btj * ISTR;
        const float* pp = base + (chunk * 4) * HW;
        float acc[4] = {0.f, 0.f, 0.f, 0.f};
        #pragma unroll
        for (int cc = 0; cc < 4; cc++) {
            const float* q = pp + cc * HW;
            acc[cc] = g.z00 * q[g.o00] + g.z01 * q[g.o01]
                    + g.z10 * q[g.o10] + g.z11 * q[g.o11];
        }
        a0 += acc[0]; a1 += acc[1]; a2 += acc[2]; a3 += acc[3];
    }

    if (t < 2 * s) {
        // final: planar store via smem bounce (conflict-free, coalesced)
        int cb = chunk * 4;
        sm[pl * 17 + cb + 0] = a0;
        sm[pl * 17 + cb + 1] = a1;
        sm[pl * 17 + cb + 2] = a2;
        sm[pl * 17 + cb + 3] = a3;
        __syncthreads();
        float* dst = iFdst + bt * ISTR;
        int pb = blockIdx.x * 64;
        #pragma unroll
        for (int r = 0; r < 4; r++) {
            int c = (tid >> 6) + r * 4;
            int i = tid & 63;
            dst[c * HW + pb + i] = sm[i * 17 + c];
        }
    } else {
        *(float4*)(iscr + bt * ISTR + (size_t)p * 16 + chunk * 4) =
            make_float4(a0, a1, a2, a3);
    }
}

extern "C" void kernel_launch(void* const* d_in, const int* in_sizes, int n_in,
                              void* d_out, int out_size)
{
    const float* flows  = (const float*)d_in[0];
    const float* images = (const float*)d_in[1];
    if (n_in >= 2 && in_sizes[0] > in_sizes[1]) {
        flows  = (const float*)d_in[1];
        images = (const float*)d_in[0];
    }
    float* out = (float*)d_out;

    float *iS0, *iS1, *fS0, *fS1, *fF;
    cudaGetSymbolAddress((void**)&iS0, g_iS0);
    cudaGetSymbolAddress((void**)&iS1, g_iS1);
    cudaGetSymbolAddress((void**)&fS0, g_fS0);
    cudaGetSymbolAddress((void**)&fS1, g_fS1);
    cudaGetSymbolAddress((void**)&fF,  g_fF);

    // t = 0 passthrough
    copy_t0_kernel<<<512, 256>>>(images, flows, out, fF);

    // s = 1
    flow_step_kernel<<<dim3(64, B * 31), 256>>>(flows, fF, flows, fF, fS0, 1);
    img_step1_kernel<<<dim3(64, B * 31), 256>>>(images, flows, out, iS0);

    // s = 2
    flow_step_kernel<<<dim3(64, B * 30), 256>>>(flows, fF, fS0, fF, fS1, 2);
    img_step_kernel <<<dim3(256, B * 30), 256>>>(images, out, iS0, out, iS1, fS0, 2);

    // s = 4
    flow_step_kernel<<<dim3(64, B * 28), 256>>>(flows, fF, fS1, fF, fS0, 4);
    img_step_kernel <<<dim3(256, B * 28), 256>>>(images, out, iS1, out, iS0, fS1, 4);

    // s = 8
    flow_step_kernel<<<dim3(64, B * 24), 256>>>(flows, fF, fS0, fF, fS1, 8);
    img_step_kernel <<<dim3(256, B * 24), 256>>>(images, out, iS0, out, iS1, fS0, 8);

    // s = 16 (no flow update needed; all outputs final -> d_out)
    img_step_kernel <<<dim3(256, B * 16), 256>>>(images, out, iS1, out, iS0, fS1, 16);
}

// round 4
// speedup vs baseline: 1.4859x; 1.4452x over previous
#include <cuda_runtime.h>
#include <cuda_bf16.h>
#include <cstdint>

// flows:  [B=4, L=32, 2,  H=128, W=128] fp32 planar input
// images: [B=4, L=32, 16, H=128, W=128] fp32 planar input/output
// Internally everything is channel-interleaved: images [bt][hw][16], flows [bt][hw][2].
// pscan: 5 doubling steps s = 1,2,4,8,16, no-copy routing:
//   step s writes t in [s,2s) -> finals buffer, t >= 2s -> alternating scratch.
//   reads j = t-s:  j==0 -> interleaved input, 1<=j<s -> finals, j>=s -> prev scratch.

constexpr int B  = 4;
constexpr int L  = 32;
constexpr int C  = 16;
constexpr int H  = 128;
constexpr int W  = 128;
constexpr int HW = H * W;
constexpr int FSTR = 2 * HW;
constexpr int ISTR = C * HW;

// Allocation-free scratch (device globals).
__device__ float g_iIn[B * L * ISTR];  // interleaved input images
__device__ float g_iF [B * L * ISTR];  // interleaved finals
__device__ float g_iS0[B * L * ISTR];  // ping
__device__ float g_iS1[B * L * ISTR];  // pong
__device__ float g_fIn[B * L * FSTR];
__device__ float g_fF [B * L * FSTR];
__device__ float g_fS0[B * L * FSTR];
__device__ float g_fS1[B * L * FSTR];

struct GridS {
    int o00, o01, o10, o11;
    float w00, w01, w10, w11;   // border-pad weights (flows)
    float z00, z01, z10, z11;   // zeros-pad weights (images)
};

__device__ __forceinline__ GridS make_grid(float fx, float fyv, int w, int h)
{
    GridS g;
    float gx = ((float)w + 0.5f) * (2.0f / W) - 1.0f + fx;
    float gy = ((float)h + 0.5f) * (2.0f / H) - 1.0f + fyv;

    float r = fmodf(gx + 1.0f, 2.0f);
    if (r < 0.0f) r += 2.0f;
    float gxw = r - 1.0f;

    float x  = (gxw + 1.0f) * (0.5f * W) - 0.5f;
    float yy = (gy  + 1.0f) * (0.5f * H) - 0.5f;

    float x0f = floorf(x);
    float y0f = floorf(yy);
    float wx = x - x0f;
    float wy = yy - y0f;
    int x0 = (int)x0f, y0 = (int)y0f;
    int x1 = x0 + 1,   y1 = y0 + 1;

    int x0c = min(max(x0, 0), W - 1);
    int x1c = min(max(x1, 0), W - 1);
    int y0c = min(max(y0, 0), H - 1);
    int y1c = min(max(y1, 0), H - 1);

    g.w00 = (1.0f - wx) * (1.0f - wy);
    g.w01 = wx * (1.0f - wy);
    g.w10 = (1.0f - wx) * wy;
    g.w11 = wx * wy;

    g.o00 = y0c * W + x0c;
    g.o01 = y0c * W + x1c;
    g.o10 = y1c * W + x0c;
    g.o11 = y1c * W + x1c;

    bool vx0 = (x0 >= 0) && (x0 < W);
    bool vx1 = (x1 >= 0) && (x1 < W);
    bool vy0 = (y0 >= 0) && (y0 < H);
    bool vy1 = (y1 >= 0) && (y1 < H);
    g.z00 = (vy0 && vx0) ? g.w00 : 0.0f;
    g.z01 = (vy0 && vx1) ? g.w01 : 0.0f;
    g.z10 = (vy1 && vx0) ? g.w10 : 0.0f;
    g.z11 = (vy1 && vx1) ? g.w11 : 0.0f;
    return g;
}

// ---- pre-transpose images: planar -> interleaved -----------------------------
__global__ __launch_bounds__(256)
void img_pre_kernel(const float* __restrict__ src, float* __restrict__ dst)
{
    __shared__ float sm[64 * 17];
    int tid = threadIdx.x;
    int pb = blockIdx.x * 64;
    size_t bt = blockIdx.y;
    const float* s = src + bt * ISTR;
    float* d = dst + bt * ISTR;
    #pragma unroll
    for (int rr = 0; rr < 4; rr++) {
        int c = (tid >> 6) + rr * 4;
        int i = tid & 63;
        sm[i * 17 + c] = s[c * HW + pb + i];
    }
    __syncthreads();
    #pragma unroll
    for (int k = 0; k < 4; k++) {
        int idx = tid + k * 256;
        d[(size_t)pb * 16 + idx] = sm[(idx >> 4) * 17 + (idx & 15)];
    }
}

// ---- pre-transpose flows: planar -> interleaved float2 -----------------------
__global__ __launch_bounds__(256)
void flow_pre_kernel(const float* __restrict__ src, float* __restrict__ dst)
{
    int p = blockIdx.x * 256 + threadIdx.x;
    size_t bt = blockIdx.y;
    const float* s = src + bt * FSTR;
    ((float2*)(dst + bt * FSTR))[p] = make_float2(s[p], s[HW + p]);
}

// ---- fused pscan step: flows + images, all interleaved -----------------------
__global__ __launch_bounds__(256)
void fused_step_kernel(const float* __restrict__ iIn, const float* iF,
                       const float* __restrict__ iprev, float* __restrict__ iscr,
                       const float* __restrict__ fIn, const float* fF,
                       const float* __restrict__ fprev, float* __restrict__ fscr,
                       int s, int do_flow)
{
    int tid = threadIdx.x;
    int chunk = tid & 3;
    int pl = tid >> 2;
    int p = blockIdx.x * 64 + pl;          // gridDim.x = 256
    int Ls = L - s;
    int y = blockIdx.y;
    int b = y / Ls, trel = y % Ls;
    int t = s + trel, j = trel;
    size_t bt  = (size_t)(b * L + t);
    size_t btj = (size_t)(b * L + j);

    float2 fc = ((const float2*)(fprev + bt * FSTR))[p];
    int w = p & (W - 1), h = p >> 7;
    GridS g = make_grid(fc.x, fc.y, w, h);

    bool final_t = (t < 2 * s);

    // ---- image: 4 channels per thread, interleaved float4 taps ----
    float4 cv = *(const float4*)(iprev + bt * ISTR + (size_t)p * 16 + chunk * 4);
    const float* ibase = (j == 0) ? iIn : (j < s) ? iF : iprev;
    const float* srcp = ibase + btj * ISTR + chunk * 4;
    float4 v00 = *(const float4*)(srcp + (size_t)g.o00 * 16);
    float4 v01 = *(const float4*)(srcp + (size_t)g.o01 * 16);
    float4 v10 = *(const float4*)(srcp + (size_t)g.o10 * 16);
    float4 v11 = *(const float4*)(srcp + (size_t)g.o11 * 16);
    float a0 = cv.x + g.z00 * v00.x + g.z01 * v01.x + g.z10 * v10.x + g.z11 * v11.x;
    float a1 = cv.y + g.z00 * v00.y + g.z01 * v01.y + g.z10 * v10.y + g.z11 * v11.y;
    float a2 = cv.z + g.z00 * v00.z + g.z01 * v01.z + g.z10 * v10.z + g.z11 * v11.z;
    float a3 = cv.w + g.z00 * v00.w + g.z01 * v01.w + g.z10 * v10.w + g.z11 * v11.w;

    float* idst = (float*)(final_t ? iF : iscr);
    *(float4*)(idst + bt * ISTR + (size_t)p * 16 + chunk * 4) =
        make_float4(a0, a1, a2, a3);

    // ---- flow: chunk-0 lanes, interleaved float2 taps, border weights ----
    if (do_flow && chunk == 0) {
        const float* fbase = (j == 0) ? fIn : (j < s) ? fF : fprev;
        const float2* fsrc = (const float2*)(fbase + btj * FSTR);
        float2 t00 = fsrc[g.o00];
        float2 t01 = fsrc[g.o01];
        float2 t10 = fsrc[g.o10];
        float2 t11 = fsrc[g.o11];
        float nx = fc.x + g.w00 * t00.x + g.w01 * t01.x + g.w10 * t10.x + g.w11 * t11.x;
        float ny = fc.y + g.w00 * t00.y + g.w01 * t01.y + g.w10 * t10.y + g.w11 * t11.y;
        float* fdst = (float*)(final_t ? fF : fscr);
        ((float2*)(fdst + bt * FSTR))[p] = make_float2(nx, ny);
    }
}

// ---- post-transpose images: interleaved finals -> planar d_out ---------------
__global__ __launch_bounds__(256)
void img_post_kernel(const float* __restrict__ iIn, const float* __restrict__ iF,
                     float* __restrict__ out)
{
    __shared__ float sm[64 * 17];
    int tid = threadIdx.x;
    int chunk = tid & 3;
    int pl = tid >> 2;
    int pb = blockIdx.x * 64;
    int p = pb + pl;
    size_t bt = blockIdx.y;
    int t = (int)(bt % L);
    const float* src = ((t == 0) ? iIn : iF) + bt * ISTR;

    float4 v = *(const float4*)(src + (size_t)p * 16 + chunk * 4);
    int cb = chunk * 4;
    sm[pl * 17 + cb + 0] = v.x;
    sm[pl * 17 + cb + 1] = v.y;
    sm[pl * 17 + cb + 2] = v.z;
    sm[pl * 17 + cb + 3] = v.w;
    __syncthreads();
    float* d = out + bt * ISTR;
    #pragma unroll
    for (int rr = 0; rr < 4; rr++) {
        int c = (tid >> 6) + rr * 4;
        int i = tid & 63;
        d[c * HW + pb + i] = sm[i * 17 + c];
    }
}

extern "C" void kernel_launch(void* const* d_in, const int* in_sizes, int n_in,
                              void* d_out, int out_size)
{
    const float* flows  = (const float*)d_in[0];
    const float* images = (const float*)d_in[1];
    if (n_in >= 2 && in_sizes[0] > in_sizes[1]) {
        flows  = (const float*)d_in[1];
        images = (const float*)d_in[0];
    }
    float* out = (float*)d_out;

    float *iIn, *iF, *iS0, *iS1, *fIn, *fF, *fS0, *fS1;
    cudaGetSymbolAddress((void**)&iIn, g_iIn);
    cudaGetSymbolAddress((void**)&iF,  g_iF);
    cudaGetSymbolAddress((void**)&iS0, g_iS0);
    cudaGetSymbolAddress((void**)&iS1, g_iS1);
    cudaGetSymbolAddress((void**)&fIn, g_fIn);
    cudaGetSymbolAddress((void**)&fF,  g_fF);
    cudaGetSymbolAddress((void**)&fS0, g_fS0);
    cudaGetSymbolAddress((void**)&fS1, g_fS1);

    // transpose inputs to interleaved
    img_pre_kernel <<<dim3(256, B * L), 256>>>(images, iIn);
    flow_pre_kernel<<<dim3(64,  B * L), 256>>>(flows, fIn);

    // fused pscan steps
    fused_step_kernel<<<dim3(256, B * 31), 256>>>(iIn, iF, iIn, iS0,
                                                  fIn, fF, fIn, fS0, 1, 1);
    fused_step_kernel<<<dim3(256, B * 30), 256>>>(iIn, iF, iS0, iS1,
                                                  fIn, fF, fS0, fS1, 2, 1);
    fused_step_kernel<<<dim3(256, B * 28), 256>>>(iIn, iF, iS1, iS0,
                                                  fIn, fF, fS1, fS0, 4, 1);
    fused_step_kernel<<<dim3(256, B * 24), 256>>>(iIn, iF, iS0, iS1,
                                                  fIn, fF, fS0, fS1, 8, 1);
    fused_step_kernel<<<dim3(256, B * 16), 256>>>(iIn, iF, iS1, iS0,
                                                  fIn, fF, fS1, fS0, 16, 0);

    // transpose finals to planar output
    img_post_kernel<<<dim3(256, B * L), 256>>>(iIn, iF, out);
}